// round 16
// baseline (speedup 1.0000x reference)
#include <cuda_runtime.h>
#include <cuda_fp16.h>
#include <cstdint>

// Problem constants
#define NSEQ 16384   // B*Ns
#define TLEN 128
#define CDIM 25
#define PDIM 20
#define HDIM 25
// Gate-column layout (N=96):
//   cols 0..63 : r/z interleaved by unit-block: block b (units 8b..8b+7):
//                r at cols 16b..16b+7, z at cols 16b+8..16b+15
//   cols 64..95: n gate, col = 64 + unit  (stride ≡ 0 mod 8 -> D->A identity)

typedef unsigned long long ull;

// ---------------- helpers ----------------
__device__ __forceinline__ ull ffma2(ull a, ull b, ull c) {
    ull d;
    asm("fma.rn.f32x2 %0, %1, %2, %3;" : "=l"(d) : "l"(a), "l"(b), "l"(c));
    return d;
}
__device__ __forceinline__ ull fdup(float v) {
    ull r;
    asm("mov.b64 %0, {%1, %1};" : "=l"(r) : "f"(v));
    return r;
}
__device__ __forceinline__ void f2unpack(ull v, float& lo, float& hi) {
    asm("mov.b64 {%0, %1}, %2;" : "=f"(lo), "=f"(hi) : "l"(v));
}
__device__ __forceinline__ float tanhx(float x) {
    float r; asm("tanh.approx.f32 %0, %1;" : "=f"(r) : "f"(x)); return r;
}
__device__ __forceinline__ ull pkbits(float lo, float hi) {
    return (ull)__float_as_uint(lo) | ((ull)__float_as_uint(hi) << 32);
}
__device__ __forceinline__ void cpa16(uint32_t smem_addr, const void* gptr) {
    asm volatile("cp.async.cg.shared.global [%0], [%1], 16;"
                 :: "r"(smem_addr), "l"(gptr));
}
__device__ __forceinline__ void cpa_commit() {
    asm volatile("cp.async.commit_group;");
}
__device__ __forceinline__ void cpa_wait1() {
    asm volatile("cp.async.wait_group 1;");
}
__device__ __forceinline__ uint32_t s2u(const void* p) {
    uint32_t a;
    asm("{ .reg .u64 t; cvta.to.shared.u64 t, %1; cvt.u32.u64 %0, t; }"
        : "=r"(a) : "l"(p));
    return a;
}
__device__ __forceinline__ uint32_t packh2(float lo, float hi) {
    uint32_t d;
    asm("cvt.rn.f16x2.f32 %0, %1, %2;" : "=r"(d) : "f"(hi), "f"(lo));
    return d;
}
__device__ __forceinline__ uint32_t lds32(uint32_t addr) {
    uint32_t v;
    asm volatile("ld.shared.u32 %0, [%1];" : "=r"(v) : "r"(addr));
    return v;
}
// m16n8k16 f16 MMA, fp32 accum in place
__device__ __forceinline__ void mma_acc(float* d, uint32_t a0, uint32_t a1,
                                        uint32_t a2, uint32_t a3,
                                        uint32_t b0, uint32_t b1) {
    asm volatile(
        "mma.sync.aligned.m16n8k16.row.col.f32.f16.f16.f32 "
        "{%0,%1,%2,%3}, {%4,%5,%6,%7}, {%8,%9}, {%0,%1,%2,%3};"
        : "+f"(d[0]), "+f"(d[1]), "+f"(d[2]), "+f"(d[3])
        : "r"(a0), "r"(a1), "r"(a2), "r"(a3), "r"(b0), "r"(b1));
}

// col -> (gate, unit) for the r/z region (c < 64)
__device__ __forceinline__ void rz_decode(int c, int& gate, int& u) {
    int b = c >> 4, w = c & 15;
    gate = w >> 3;
    u = 8 * b + (w & 7);
}

// ---------------- device scratch (static: no allocation) ----------------
__device__ ull    g_pW1[CDIM * 10];   // f32x2-packed W1 for ktp
__device__ ull    g_pb1[10];
__device__ __half g_Bih16[96 * 16];   // [col][k<16] = p dims 0..15 side
__device__ __half g_Bhh16[96 * 32];   // [col][k]: k<25 Whh, k25 bias, k26..29 Wih ovf (rz)
__device__ __half g_Bio16[32 * 16];   // n-gate overflow: [u][k']: k'<4 Wih 16..19, k'4 bih_n
__device__ __half g_p[(size_t)TLEN * NSEQ * 24];   // 100 MB: p fp16, [t][n][24]

// ---------------- prep (parallel) ----------------
__global__ void prep_kernel(const float* __restrict__ W1, const float* __restrict__ b1,
                            const float* __restrict__ Wih, const float* __restrict__ Whh,
                            const float* __restrict__ bih, const float* __restrict__ bhh) {
    int gid = blockIdx.x * blockDim.x + threadIdx.x;
    int stride = gridDim.x * blockDim.x;

    for (int i = gid; i < CDIM * 10; i += stride) {
        int k = i / 10, jp = i % 10;
        g_pW1[i] = pkbits(W1[(2 * jp) * CDIM + k], W1[(2 * jp + 1) * CDIM + k]);
    }
    for (int i = gid; i < 10; i += stride)
        g_pb1[i] = pkbits(b1[2 * i], b1[2 * i + 1]);

    for (int i = gid; i < 96 * 16; i += stride) {
        int c = i / 16, k = i % 16;
        float v = 0.f;
        if (c < 64) {
            int gate, u; rz_decode(c, gate, u);
            if (u < 25) v = 0.5f * Wih[(gate * 25 + u) * PDIM + k];
        } else {
            int u = c - 64;
            if (u < 25) v = Wih[(50 + u) * PDIM + k];
        }
        g_Bih16[i] = __float2half_rn(v);
    }
    for (int i = gid; i < 96 * 32; i += stride) {
        int c = i / 32, k = i % 32;
        float v = 0.f;
        if (c < 64) {
            int gate, u; rz_decode(c, gate, u);
            if (u < 25) {
                if (k < 25)       v = 0.5f * Whh[(gate * 25 + u) * HDIM + k];
                else if (k == 25) v = 0.5f * (bih[gate * 25 + u] + bhh[gate * 25 + u]);
                else if (k < 30)  v = 0.5f * Wih[(gate * 25 + u) * PDIM + (k - 10)]; // p16..19
            }
        } else {
            int u = c - 64;
            if (u < 25) {
                if (k < 25)       v = Whh[(50 + u) * HDIM + k];
                else if (k == 25) v = bhh[50 + u];
            }
        }
        g_Bhh16[i] = __float2half_rn(v);
    }
    for (int i = gid; i < 32 * 16; i += stride) {
        int u = i / 16, k = i % 16;
        float v = 0.f;
        if (u < 25) {
            if (k < 4)       v = Wih[(50 + u) * PDIM + 16 + k];
            else if (k == 4) v = bih[50 + u];
        }
        g_Bio16[i] = __float2half_rn(v);
    }
}

// ---------------- ktp: p = leakyrelu(x@W1^T + b1) -> fp16 [t][n][24] ----------------
__global__ __launch_bounds__(128, 1) void ktp_kernel(const float* __restrict__ x) {
    __shared__ ull sW1[CDIM * 10];
    __shared__ ull sb1[10];
    for (int i = threadIdx.x; i < CDIM * 10; i += 128) sW1[i] = g_pW1[i];
    for (int i = threadIdx.x; i < 10; i += 128) sb1[i] = g_pb1[i];
    __syncthreads();

    int n = blockIdx.x * 128 + threadIdx.x;
    int t0 = blockIdx.y * 2;

    const float2* xp = reinterpret_cast<const float2*>(x + ((size_t)n * TLEN + t0) * CDIM);
    float xv[50];
#pragma unroll
    for (int i = 0; i < 25; i++) {
        float2 v = __ldg(xp + i);
        xv[2 * i] = v.x; xv[2 * i + 1] = v.y;
    }

    ull pa0[10], pa1[10];
#pragma unroll
    for (int j = 0; j < 10; j++) { pa0[j] = sb1[j]; pa1[j] = sb1[j]; }
#pragma unroll
    for (int k = 0; k < CDIM; k++) {
        ull d0 = fdup(xv[k]);
        ull d1 = fdup(xv[25 + k]);
        const ulonglong2* row = reinterpret_cast<const ulonglong2*>(&sW1[k * 10]);
#pragma unroll
        for (int j = 0; j < 5; j++) {
            ulonglong2 w = row[j];
            pa0[2 * j]     = ffma2(w.x, d0, pa0[2 * j]);
            pa0[2 * j + 1] = ffma2(w.y, d0, pa0[2 * j + 1]);
            pa1[2 * j]     = ffma2(w.x, d1, pa1[2 * j]);
            pa1[2 * j + 1] = ffma2(w.y, d1, pa1[2 * j + 1]);
        }
    }
    union { __half2 hh[12]; uint4 v4[3]; } o0, o1;
#pragma unroll
    for (int j = 0; j < 10; j++) {
        float a, b;
        f2unpack(pa0[j], a, b);
        o0.hh[j] = __floats2half2_rn(fmaxf(a, 0.01f * a), fmaxf(b, 0.01f * b));
        f2unpack(pa1[j], a, b);
        o1.hh[j] = __floats2half2_rn(fmaxf(a, 0.01f * a), fmaxf(b, 0.01f * b));
    }
    o0.hh[10] = o0.hh[11] = __floats2half2_rn(0.f, 0.f);
    o1.hh[10] = o1.hh[11] = __floats2half2_rn(0.f, 0.f);

    uint4* d0 = reinterpret_cast<uint4*>(g_p + ((size_t)t0 * NSEQ + n) * 24);
    uint4* d1 = reinterpret_cast<uint4*>(g_p + ((size_t)(t0 + 1) * NSEQ + n) * 24);
#pragma unroll
    for (int i = 0; i < 3; i++) { d0[i] = o0.v4[i]; d1[i] = o1.v4[i]; }
}

// ---------------- GRU scan: 40 HMMA/step, all biases ride the MMAs ----------------
__global__ __launch_bounds__(128, 1) void gru_kernel(float* __restrict__ out) {
    __shared__ __align__(16) char sP[4 * 2 * 16 * 48];   // 6 KB: 4 warps x 2 bufs x 16x48B

    const int tid = threadIdx.x;
    const int w = tid >> 5, lane = tid & 31;
    const int g = lane >> 2, tig = lane & 3;
    const int n0 = blockIdx.x * 64 + w * 16;

    // B fragments (loaded once)
    uint32_t Bih[12][2], Bhh[12][2][2], Bio[4];
    {
        const uint32_t* pih = reinterpret_cast<const uint32_t*>(g_Bih16);
        const uint32_t* phh = reinterpret_cast<const uint32_t*>(g_Bhh16);
        const uint32_t* pio = reinterpret_cast<const uint32_t*>(g_Bio16);
#pragma unroll
        for (int nf = 0; nf < 12; nf++) {
            int col = 8 * nf + g;
            Bih[nf][0] = pih[col * 8 + tig];
            Bih[nf][1] = pih[col * 8 + tig + 4];
#pragma unroll
            for (int kf = 0; kf < 2; kf++) {
                Bhh[nf][kf][0] = phh[col * 16 + 8 * kf + tig];
                Bhh[nf][kf][1] = phh[col * 16 + 8 * kf + tig + 4];
            }
        }
#pragma unroll
        for (int b = 0; b < 4; b++) Bio[b] = pio[(8 * b + g) * 8 + tig];
    }

    const uint32_t sb = s2u(sP) + w * 1536;
    const char* pg = reinterpret_cast<const char*>(g_p);

    auto prefetch = [&](int t, int buf) {
#pragma unroll
        for (int rep = 0; rep < 2; rep++) {
            int idx = lane + 32 * rep;
            if (idx < 48) {
                int row = idx / 3, part = idx % 3;
                cpa16(sb + buf * 768 + row * 48 + part * 16,
                      pg + ((size_t)t * NSEQ + n0 + row) * 48 + part * 16);
            }
        }
    };

    prefetch(0, 0);
    cpa_commit();

    float h[2][8];
#pragma unroll
    for (int r = 0; r < 2; r++)
#pragma unroll
        for (int j = 0; j < 8; j++) h[r][j] = 0.f;

    const uint32_t ONE_LO = 0x00003C00u;   // half2 (1.0, 0.0)

#pragma unroll 1
    for (int t = 0; t < TLEN; t++) {
        const int buf = t & 1;
        if (t + 1 < TLEN) prefetch(t + 1, buf ^ 1);
        cpa_commit();
        cpa_wait1();       // buf(t) ready (its group is second-newest)
        __syncwarp();      // partner lanes' copies visible

        const uint32_t base = sb + buf * 768;
        const uint32_t rg = base + g * 48, rg8 = base + (g + 8) * 48;
        uint32_t apx0 = lds32(rg + 4 * tig);
        uint32_t apx1 = lds32(rg8 + 4 * tig);
        uint32_t apx2 = lds32(rg + 4 * tig + 16);
        uint32_t apx3 = lds32(rg8 + 4 * tig + 16);
        uint32_t ovg1 = lds32(rg + 32),  ovh1 = lds32(rg8 + 32);   // p16,p17
        uint32_t ovg2 = lds32(rg + 36),  ovh2 = lds32(rg8 + 36);   // p18,p19

        // A_h fragments from current h; k-slots 25..31 repurposed:
        //   k25 = 1.0 (bias), k26..29 = p16..19 (rz overflow), k30,31 = 0
        uint32_t ah0[4], ah1[4], apo0, apo1;
        ah0[0] = packh2(h[0][0], h[0][1]);
        ah0[1] = packh2(h[1][0], h[1][1]);
        ah0[2] = packh2(h[0][2], h[0][3]);
        ah0[3] = packh2(h[1][2], h[1][3]);
        ah1[0] = packh2(h[0][4], h[0][5]);
        ah1[1] = packh2(h[1][4], h[1][5]);
        if (tig == 0) {
            ah1[2] = packh2(h[0][6], 1.0f);   // (h24, bias)
            ah1[3] = packh2(h[1][6], 1.0f);
            apo0 = ovg1; apo1 = ovh1;         // n-gate ovf: (p16,p17)
        } else if (tig == 1) {
            ah1[2] = ovg1; ah1[3] = ovh1;     // (p16,p17) at k26,27
            apo0 = ovg2; apo1 = ovh2;         // (p18,p19)
        } else if (tig == 2) {
            ah1[2] = ovg2; ah1[3] = ovh2;     // (p18,p19) at k28,29
            apo0 = ONE_LO; apo1 = ONE_LO;     // bias slot k'=4
        } else {
            ah1[2] = 0u; ah1[3] = 0u;
            apo0 = 0u; apo1 = 0u;
        }

        // per unit-block: 10 MMA + gates
#pragma unroll
        for (int b = 0; b < 4; b++) {
            float Dr[4] = {0, 0, 0, 0}, Dz[4] = {0, 0, 0, 0};
            float Dxn[4] = {0, 0, 0, 0}, Dhn[4] = {0, 0, 0, 0};
            mma_acc(Dr, apx0, apx1, apx2, apx3, Bih[2 * b][0], Bih[2 * b][1]);
            mma_acc(Dr, ah0[0], ah0[1], ah0[2], ah0[3], Bhh[2 * b][0][0], Bhh[2 * b][0][1]);
            mma_acc(Dr, ah1[0], ah1[1], ah1[2], ah1[3], Bhh[2 * b][1][0], Bhh[2 * b][1][1]);
            mma_acc(Dz, apx0, apx1, apx2, apx3, Bih[2 * b + 1][0], Bih[2 * b + 1][1]);
            mma_acc(Dz, ah0[0], ah0[1], ah0[2], ah0[3],
                    Bhh[2 * b + 1][0][0], Bhh[2 * b + 1][0][1]);
            mma_acc(Dz, ah1[0], ah1[1], ah1[2], ah1[3],
                    Bhh[2 * b + 1][1][0], Bhh[2 * b + 1][1][1]);
            mma_acc(Dxn, apx0, apx1, apx2, apx3, Bih[8 + b][0], Bih[8 + b][1]);
            mma_acc(Dxn, apo0, apo1, 0u, 0u, Bio[b], 0u);
            mma_acc(Dhn, ah0[0], ah0[1], ah0[2], ah0[3],
                    Bhh[8 + b][0][0], Bhh[8 + b][0][1]);
            mma_acc(Dhn, ah1[0], ah1[1], ah1[2], ah1[3],
                    Bhh[8 + b][1][0], Bhh[8 + b][1][1]);
#pragma unroll
            for (int r = 0; r < 2; r++) {
#pragma unroll
                for (int e = 0; e < 2; e++) {
                    int di = 2 * r + e;
                    float rr = fmaf(0.5f, tanhx(Dr[di]), 0.5f);
                    float zz = fmaf(0.5f, tanhx(Dz[di]), 0.5f);
                    float nn = tanhx(fmaf(rr, Dhn[di], Dxn[di]));
                    float& hv = h[r][2 * b + e];
                    hv = fmaf(zz, hv - nn, nn);
                }
            }
        }
    }

    // write valid units (unit = 8b + 2tig + e)
#pragma unroll
    for (int r = 0; r < 2; r++) {
        int n = n0 + g + 8 * r;
#pragma unroll
        for (int b = 0; b < 4; b++) {
#pragma unroll
            for (int e = 0; e < 2; e++) {
                int u = 8 * b + 2 * tig + e;
                if (u < 25) out[(size_t)n * HDIM + u] = h[r][2 * b + e];
            }
        }
    }
}

// ---------------- launcher ----------------
extern "C" void kernel_launch(void* const* d_in, const int* in_sizes, int n_in,
                              void* d_out, int out_size) {
    (void)in_sizes; (void)n_in; (void)out_size;
    const float* x   = (const float*)d_in[0];
    const float* W1  = (const float*)d_in[1];
    const float* b1  = (const float*)d_in[2];
    const float* Wih = (const float*)d_in[3];
    const float* Whh = (const float*)d_in[4];
    const float* bih = (const float*)d_in[5];
    const float* bhh = (const float*)d_in[6];

    prep_kernel<<<32, 256>>>(W1, b1, Wih, Whh, bih, bhh);
    ktp_kernel<<<dim3(NSEQ / 128, TLEN / 2), 128>>>(x);
    gru_kernel<<<NSEQ / 64, 128>>>((float*)d_out);
}